// round 2
// baseline (speedup 1.0000x reference)
#include <cuda_runtime.h>
#include <math.h>

#define BATCH 16
#define CHAN  256
#define NPIX  4096

typedef unsigned long long ull;

// Scratch (allocation-free: __device__ globals)
__device__ float g_energy[3u * BATCH * CHAN * CHAN];    // 12.6 MB
__device__ float g_attn[(unsigned)BATCH * CHAN * CHAN]; // 4.2 MB
__device__ float g_M[(unsigned)BATCH * CHAN * CHAN];    // 4.2 MB

// ---- packed f32x2 helpers (FFMA2: 2 IEEE fp32 FMAs per instruction) --------
__device__ __forceinline__ ull bcast2(float v) {
    ull r;
    asm("mov.b64 %0, {%1, %1};" : "=l"(r) : "f"(v));
    return r;
}
__device__ __forceinline__ void fma2(ull& d, ull a, ull b) {
    asm("fma.rn.f32x2 %0, %1, %2, %0;" : "+l"(d) : "l"(a), "l"(b));
}
__device__ __forceinline__ float2 unpack2(ull v) {
    float2 r;
    asm("mov.b64 {%0, %1}, %2;" : "=f"(r.x), "=f"(r.y) : "l"(v));
    return r;
}

// ---------------------------------------------------------------------------
// Kernel 1: energy[s][b][c][d] = sum_n x[b,c,n] * src_s[b,d,n]   (NT GEMM)
// Tile TM=128 x TN=64 x TK=16, 256 threads, 8x4 micro-tile.
// Accumulators packed along m (m-pairs come free from LDS.128); b broadcast
// packed with one MOV each (ALU pipe).
// ---------------------------------------------------------------------------
__global__ __launch_bounds__(256, 2)
void energy_kernel(const float* __restrict__ x, const float* __restrict__ y,
                   const float* __restrict__ z)
{
    constexpr int TM = 128, TN = 64, TK = 16;
    constexpr int PA = 132, PB = 68;
    __shared__ float As[TK * PA];
    __shared__ float Bs[TK * PB];

    int id = blockIdx.x;
    int t  = id & 7;
    int bs = id >> 3;
    int b  = bs & 15;
    int s  = bs >> 4;
    int cBase = (t >> 2) * TM;
    int dBase = (t & 3) * TN;

    const float* A = x + (size_t)b * (CHAN * NPIX);
    const float* S = (s == 0 ? x : (s == 1 ? y : z)) + (size_t)b * (CHAN * NPIX);

    int tid = threadIdx.x;
    int ty = tid >> 4, tx = tid & 15;
    int m0 = ty * 8, n0 = tx * 4;

    int mld = tid >> 2;
    int kc  = (tid & 3) * 4;

    const float* pA0 = A + (size_t)(cBase + mld) * NPIX + kc;
    const float* pA1 = pA0 + (size_t)64 * NPIX;
    const float* pB  = S + (size_t)(dBase + mld) * NPIX + kc;

    float4 ra0 = *(const float4*)pA0;
    float4 ra1 = *(const float4*)pA1;
    float4 rb  = *(const float4*)pB;

    // acc2[mp][j]: packed pair (rows 2mp, 2mp+1) x col j
    ull acc2[4][4];
    #pragma unroll
    for (int i = 0; i < 4; i++)
        #pragma unroll
        for (int j = 0; j < 4; j++) acc2[i][j] = 0ull;

    for (int kb = 0; kb < NPIX; kb += TK) {
        As[(kc+0)*PA + mld] = ra0.x;
        As[(kc+1)*PA + mld] = ra0.y;
        As[(kc+2)*PA + mld] = ra0.z;
        As[(kc+3)*PA + mld] = ra0.w;
        As[(kc+0)*PA + 64 + mld] = ra1.x;
        As[(kc+1)*PA + 64 + mld] = ra1.y;
        As[(kc+2)*PA + 64 + mld] = ra1.z;
        As[(kc+3)*PA + 64 + mld] = ra1.w;
        Bs[(kc+0)*PB + mld] = rb.x;
        Bs[(kc+1)*PB + mld] = rb.y;
        Bs[(kc+2)*PB + mld] = rb.z;
        Bs[(kc+3)*PB + mld] = rb.w;
        __syncthreads();

        if (kb + TK < NPIX) {
            pA0 += TK; pA1 += TK; pB += TK;
            ra0 = *(const float4*)pA0;
            ra1 = *(const float4*)pA1;
            rb  = *(const float4*)pB;
        }

        #pragma unroll
        for (int k = 0; k < TK; k++) {
            // 8 m-values as 4 packed pairs (free reinterpret of LDS.128)
            ulonglong2 am0 = *(const ulonglong2*)&As[k*PA + m0];
            ulonglong2 am1 = *(const ulonglong2*)&As[k*PA + m0 + 4];
            ull ap[4] = {am0.x, am0.y, am1.x, am1.y};
            float4 bq = *(const float4*)&Bs[k*PB + n0];
            ull bb[4] = {bcast2(bq.x), bcast2(bq.y), bcast2(bq.z), bcast2(bq.w)};
            #pragma unroll
            for (int i = 0; i < 4; i++)
                #pragma unroll
                for (int j = 0; j < 4; j++)
                    fma2(acc2[i][j], ap[i], bb[j]);
        }
        __syncthreads();
    }

    float* E = g_energy + ((size_t)s * BATCH + b) * (CHAN * CHAN);
    #pragma unroll
    for (int mp = 0; mp < 4; mp++) {
        float2 c0 = unpack2(acc2[mp][0]);
        float2 c1 = unpack2(acc2[mp][1]);
        float2 c2 = unpack2(acc2[mp][2]);
        float2 c3 = unpack2(acc2[mp][3]);
        int r0 = cBase + m0 + 2*mp;
        *(float4*)&E[(size_t)r0 * CHAN + dBase + n0] =
            make_float4(c0.x, c1.x, c2.x, c3.x);
        *(float4*)&E[(size_t)(r0+1) * CHAN + dBase + n0] =
            make_float4(c0.y, c1.y, c2.y, c3.y);
    }
}

// ---------------------------------------------------------------------------
// Kernel 2: attn[b][c][:] = sum_s softmax(rowmax(E_s[b][c]) - E_s[b][c])
// One WARP per (b,c) row; 8 elements per lane; shuffle reductions only.
// Same arithmetic path as reference (m1, then max of m1-e).
// ---------------------------------------------------------------------------
__global__ __launch_bounds__(256)
void softmax_sum_kernel()
{
    int gwarp = (blockIdx.x * blockDim.x + threadIdx.x) >> 5;  // row = b*CHAN+c
    int lane  = threadIdx.x & 31;

    float acc[8];
    #pragma unroll
    for (int i = 0; i < 8; i++) acc[i] = 0.f;

    #pragma unroll
    for (int s = 0; s < 3; s++) {
        const float* row = g_energy + ((size_t)s * BATCH * CHAN + gwarp) * CHAN;
        float4 e0 = *(const float4*)&row[lane * 8];
        float4 e1 = *(const float4*)&row[lane * 8 + 4];
        float e[8] = {e0.x, e0.y, e0.z, e0.w, e1.x, e1.y, e1.z, e1.w};

        float m1 = e[0];
        #pragma unroll
        for (int i = 1; i < 8; i++) m1 = fmaxf(m1, e[i]);
        #pragma unroll
        for (int o = 16; o > 0; o >>= 1)
            m1 = fmaxf(m1, __shfl_xor_sync(0xffffffffu, m1, o));

        float v[8], m2 = -3.402823466e38f;
        #pragma unroll
        for (int i = 0; i < 8; i++) { v[i] = m1 - e[i]; m2 = fmaxf(m2, v[i]); }
        #pragma unroll
        for (int o = 16; o > 0; o >>= 1)
            m2 = fmaxf(m2, __shfl_xor_sync(0xffffffffu, m2, o));

        float p[8], Ssum = 0.f;
        #pragma unroll
        for (int i = 0; i < 8; i++) { p[i] = expf(v[i] - m2); Ssum += p[i]; }
        #pragma unroll
        for (int o = 16; o > 0; o >>= 1)
            Ssum += __shfl_xor_sync(0xffffffffu, Ssum, o);

        float inv = 1.f / Ssum;
        #pragma unroll
        for (int i = 0; i < 8; i++) acc[i] += p[i] * inv;
    }

    float* out = g_attn + (size_t)gwarp * CHAN + lane * 8;
    *(float4*)&out[0] = make_float4(acc[0], acc[1], acc[2], acc[3]);
    *(float4*)&out[4] = make_float4(acc[4], acc[5], acc[6], acc[7]);
}

// ---------------------------------------------------------------------------
// Kernels 3/4: TN GEMM, C[m][n] = sum_k A[m][k]*B[k][n], K=256.
// 4x8 micro-tile; accumulators packed along n (n-pairs free from LDS.128 of
// the natural-layout B tile); a broadcast via MOV.
// ---------------------------------------------------------------------------
template<int NCOLS, bool FINAL>
__global__ __launch_bounds__(256, 2)
void gemm_tn(const float* __restrict__ Ab, long aStride,
             const float* __restrict__ Bb, long bStride,
             float* __restrict__ Ob,
             const float* __restrict__ bias,
             const float* __restrict__ gamma_p,
             const float* __restrict__ resid)
{
    constexpr int TM = 64, TN = 128, TK = 16, Kdim = 256, PA = 68;
    constexpr int NT = NCOLS / TN;
    __shared__ float As[TK * PA];
    __shared__ float Bs[TK * TN];

    int id = blockIdx.x;
    int nt = id % NT; id /= NT;
    int mt = id & 3;
    int b  = id >> 2;
    int mBase = mt * TM, nBase = nt * TN;

    const float* A = Ab + (size_t)b * aStride;
    const float* B = Bb + (size_t)b * bStride;
    float* O = Ob + (size_t)b * ((size_t)CHAN * NCOLS);
    const float* R = FINAL ? (resid + (size_t)b * ((size_t)CHAN * NCOLS)) : nullptr;

    int tid = threadIdx.x;
    int ty = tid >> 4, tx = tid & 15;
    int m0 = ty * 4, n0 = tx * 4;

    int mldA = tid >> 2, kcA = (tid & 3) * 4;
    int krB = tid >> 5, nvB = tid & 31;

    const float* pA  = A + (size_t)(mBase + mldA) * Kdim + kcA;
    const float* pB0 = B + (size_t)krB * NCOLS + nBase + nvB * 4;
    const float* pB1 = pB0 + (size_t)8 * NCOLS;

    float4 ra  = *(const float4*)pA;
    float4 rb0 = *(const float4*)pB0;
    float4 rb1 = *(const float4*)pB1;

    // acc2[i][np]: row i x packed col-pair np
    //   np=0: cols n0+0,1   np=1: cols n0+2,3
    //   np=2: cols 64+n0+0,1  np=3: cols 64+n0+2,3
    ull acc2[4][4];
    #pragma unroll
    for (int i = 0; i < 4; i++)
        #pragma unroll
        for (int j = 0; j < 4; j++) acc2[i][j] = 0ull;

    for (int kb = 0; kb < Kdim; kb += TK) {
        As[(kcA+0)*PA + mldA] = ra.x;
        As[(kcA+1)*PA + mldA] = ra.y;
        As[(kcA+2)*PA + mldA] = ra.z;
        As[(kcA+3)*PA + mldA] = ra.w;
        *(float4*)&Bs[krB * TN + nvB * 4]       = rb0;
        *(float4*)&Bs[(krB + 8) * TN + nvB * 4] = rb1;
        __syncthreads();

        if (kb + TK < Kdim) {
            pA += TK; pB0 += (size_t)TK * NCOLS; pB1 += (size_t)TK * NCOLS;
            ra  = *(const float4*)pA;
            rb0 = *(const float4*)pB0;
            rb1 = *(const float4*)pB1;
        }

        #pragma unroll
        for (int k = 0; k < TK; k++) {
            float4 a4 = *(const float4*)&As[k*PA + m0];
            ull aa[4] = {bcast2(a4.x), bcast2(a4.y), bcast2(a4.z), bcast2(a4.w)};
            ulonglong2 bp0 = *(const ulonglong2*)&Bs[k*TN + n0];
            ulonglong2 bp1 = *(const ulonglong2*)&Bs[k*TN + 64 + n0];
            ull bp[4] = {bp0.x, bp0.y, bp1.x, bp1.y};
            #pragma unroll
            for (int i = 0; i < 4; i++)
                #pragma unroll
                for (int j = 0; j < 4; j++)
                    fma2(acc2[i][j], aa[i], bp[j]);
        }
        __syncthreads();
    }

    float gamma = gamma_p[0];
    #pragma unroll
    for (int i = 0; i < 4; i++) {
        int row = mBase + m0 + i;
        size_t base = (size_t)row * NCOLS + nBase + n0;
        float2 c0 = unpack2(acc2[i][0]);
        float2 c1 = unpack2(acc2[i][1]);
        float2 c2 = unpack2(acc2[i][2]);
        float2 c3 = unpack2(acc2[i][3]);
        if (FINAL) {
            float gb = gamma * bias[row];
            float4 r0 = *(const float4*)&R[base];
            float4 r1 = *(const float4*)&R[base + 64];
            *(float4*)&O[base] = make_float4(
                c0.x + gb + r0.x, c0.y + gb + r0.y,
                c1.x + gb + r0.z, c1.y + gb + r0.w);
            *(float4*)&O[base + 64] = make_float4(
                c2.x + gb + r1.x, c2.y + gb + r1.y,
                c3.x + gb + r1.z, c3.y + gb + r1.w);
        } else {
            *(float4*)&O[base] = make_float4(
                gamma*c0.x, gamma*c0.y, gamma*c1.x, gamma*c1.y);
            *(float4*)&O[base + 64] = make_float4(
                gamma*c2.x, gamma*c2.y, gamma*c3.x, gamma*c3.y);
        }
    }
}

// ---------------------------------------------------------------------------
extern "C" void kernel_launch(void* const* d_in, const int* in_sizes, int n_in,
                              void* d_out, int out_size)
{
    const float* x      = (const float*)d_in[0];
    const float* y      = (const float*)d_in[1];
    const float* z      = (const float*)d_in[2];
    const float* conv_w = (const float*)d_in[3];
    const float* conv_b = (const float*)d_in[4];
    const float* gamma  = (const float*)d_in[5];
    float* out = (float*)d_out;

    float *pAttn, *pM;
    cudaGetSymbolAddress((void**)&pAttn, g_attn);
    cudaGetSymbolAddress((void**)&pM, g_M);

    // 1) three energy GEMMs: 384 CTAs
    energy_kernel<<<3 * BATCH * 8, 256>>>(x, y, z);
    // 2) softmax + sum over sources: 4096 rows, 1 warp each
    softmax_sum_kernel<<<BATCH * CHAN / 8, 256>>>();
    // 3) M_b = gamma * conv_w @ attn_b
    gemm_tn<CHAN, false><<<BATCH * 4 * 2, 256>>>(
        conv_w, 0, pAttn, (long)CHAN * CHAN, pM, nullptr, gamma, nullptr);
    // 4) out = M_b @ x_b + gamma*conv_b + x
    gemm_tn<NPIX, true><<<BATCH * 4 * 32, 256>>>(
        pM, (long)CHAN * CHAN, x, (long)CHAN * NPIX, out, conv_b, gamma, x);
}

// round 3
// speedup vs baseline: 1.6448x; 1.6448x over previous
#include <cuda_runtime.h>
#include <math.h>

#define BATCH 16
#define CHAN  256
#define NPIX  4096

typedef unsigned long long ull;

// Scratch (allocation-free: __device__ globals)
__device__ float g_energy[3u * BATCH * CHAN * CHAN];    // 12.6 MB
__device__ float g_attn[(unsigned)BATCH * CHAN * CHAN]; // 4.2 MB
__device__ float g_M[(unsigned)BATCH * CHAN * CHAN];    // 4.2 MB

// ---- packed f32x2 helpers (FFMA2: 2 IEEE fp32 FMAs per instruction) --------
__device__ __forceinline__ ull bcast2(float v) {
    ull r;
    asm("mov.b64 %0, {%1, %1};" : "=l"(r) : "f"(v));
    return r;
}
__device__ __forceinline__ void fma2(ull& d, ull a, ull b) {
    asm("fma.rn.f32x2 %0, %1, %2, %0;" : "+l"(d) : "l"(a), "l"(b));
}
__device__ __forceinline__ float2 unpack2(ull v) {
    float2 r;
    asm("mov.b64 {%0, %1}, %2;" : "=f"(r.x), "=f"(r.y) : "l"(v));
    return r;
}

// ---------------------------------------------------------------------------
// Kernel 1: energy[s][b][c][d] = sum_n x[b,c,n] * src_s[b,d,n]   (NT GEMM)
// Tile TM=128 x TN=64 x TK=16, 256 threads, 8x4 micro-tile.
// Accumulators packed along m (m-pairs come free from LDS.128); b broadcast
// packed with one MOV each (ALU pipe).
// ---------------------------------------------------------------------------
__global__ __launch_bounds__(256, 2)
void energy_kernel(const float* __restrict__ x, const float* __restrict__ y,
                   const float* __restrict__ z)
{
    constexpr int TM = 128, TN = 64, TK = 16;
    constexpr int PA = 132, PB = 68;
    __shared__ float As[TK * PA];
    __shared__ float Bs[TK * PB];

    int id = blockIdx.x;
    int t  = id & 7;
    int bs = id >> 3;
    int b  = bs & 15;
    int s  = bs >> 4;
    int cBase = (t >> 2) * TM;
    int dBase = (t & 3) * TN;

    const float* A = x + (size_t)b * (CHAN * NPIX);
    const float* S = (s == 0 ? x : (s == 1 ? y : z)) + (size_t)b * (CHAN * NPIX);

    int tid = threadIdx.x;
    int ty = tid >> 4, tx = tid & 15;
    int m0 = ty * 8, n0 = tx * 4;

    int mld = tid >> 2;
    int kc  = (tid & 3) * 4;

    const float* pA0 = A + (size_t)(cBase + mld) * NPIX + kc;
    const float* pA1 = pA0 + (size_t)64 * NPIX;
    const float* pB  = S + (size_t)(dBase + mld) * NPIX + kc;

    float4 ra0 = *(const float4*)pA0;
    float4 ra1 = *(const float4*)pA1;
    float4 rb  = *(const float4*)pB;

    // acc2[mp][j]: packed pair (rows 2mp, 2mp+1) x col j
    ull acc2[4][4];
    #pragma unroll
    for (int i = 0; i < 4; i++)
        #pragma unroll
        for (int j = 0; j < 4; j++) acc2[i][j] = 0ull;

    for (int kb = 0; kb < NPIX; kb += TK) {
        As[(kc+0)*PA + mld] = ra0.x;
        As[(kc+1)*PA + mld] = ra0.y;
        As[(kc+2)*PA + mld] = ra0.z;
        As[(kc+3)*PA + mld] = ra0.w;
        As[(kc+0)*PA + 64 + mld] = ra1.x;
        As[(kc+1)*PA + 64 + mld] = ra1.y;
        As[(kc+2)*PA + 64 + mld] = ra1.z;
        As[(kc+3)*PA + 64 + mld] = ra1.w;
        Bs[(kc+0)*PB + mld] = rb.x;
        Bs[(kc+1)*PB + mld] = rb.y;
        Bs[(kc+2)*PB + mld] = rb.z;
        Bs[(kc+3)*PB + mld] = rb.w;
        __syncthreads();

        if (kb + TK < NPIX) {
            pA0 += TK; pA1 += TK; pB += TK;
            ra0 = *(const float4*)pA0;
            ra1 = *(const float4*)pA1;
            rb  = *(const float4*)pB;
        }

        #pragma unroll
        for (int k = 0; k < TK; k++) {
            // 8 m-values as 4 packed pairs (free reinterpret of LDS.128)
            ulonglong2 am0 = *(const ulonglong2*)&As[k*PA + m0];
            ulonglong2 am1 = *(const ulonglong2*)&As[k*PA + m0 + 4];
            ull ap[4] = {am0.x, am0.y, am1.x, am1.y};
            float4 bq = *(const float4*)&Bs[k*PB + n0];
            ull bb[4] = {bcast2(bq.x), bcast2(bq.y), bcast2(bq.z), bcast2(bq.w)};
            #pragma unroll
            for (int i = 0; i < 4; i++)
                #pragma unroll
                for (int j = 0; j < 4; j++)
                    fma2(acc2[i][j], ap[i], bb[j]);
        }
        __syncthreads();
    }

    float* E = g_energy + ((size_t)s * BATCH + b) * (CHAN * CHAN);
    #pragma unroll
    for (int mp = 0; mp < 4; mp++) {
        float2 c0 = unpack2(acc2[mp][0]);
        float2 c1 = unpack2(acc2[mp][1]);
        float2 c2 = unpack2(acc2[mp][2]);
        float2 c3 = unpack2(acc2[mp][3]);
        int r0 = cBase + m0 + 2*mp;
        *(float4*)&E[(size_t)r0 * CHAN + dBase + n0] =
            make_float4(c0.x, c1.x, c2.x, c3.x);
        *(float4*)&E[(size_t)(r0+1) * CHAN + dBase + n0] =
            make_float4(c0.y, c1.y, c2.y, c3.y);
    }
}

// ---------------------------------------------------------------------------
// Kernel 2: attn[b][c][:] = sum_s softmax(rowmax(E_s[b][c]) - E_s[b][c])
// One WARP per (b,c) row; 8 elements per lane; shuffle reductions only.
// Same arithmetic path as reference (m1, then max of m1-e).
// ---------------------------------------------------------------------------
__global__ __launch_bounds__(256)
void softmax_sum_kernel()
{
    int gwarp = (blockIdx.x * blockDim.x + threadIdx.x) >> 5;  // row = b*CHAN+c
    int lane  = threadIdx.x & 31;

    float acc[8];
    #pragma unroll
    for (int i = 0; i < 8; i++) acc[i] = 0.f;

    #pragma unroll
    for (int s = 0; s < 3; s++) {
        const float* row = g_energy + ((size_t)s * BATCH * CHAN + gwarp) * CHAN;
        float4 e0 = *(const float4*)&row[lane * 8];
        float4 e1 = *(const float4*)&row[lane * 8 + 4];
        float e[8] = {e0.x, e0.y, e0.z, e0.w, e1.x, e1.y, e1.z, e1.w};

        float m1 = e[0];
        #pragma unroll
        for (int i = 1; i < 8; i++) m1 = fmaxf(m1, e[i]);
        #pragma unroll
        for (int o = 16; o > 0; o >>= 1)
            m1 = fmaxf(m1, __shfl_xor_sync(0xffffffffu, m1, o));

        float v[8], m2 = -3.402823466e38f;
        #pragma unroll
        for (int i = 0; i < 8; i++) { v[i] = m1 - e[i]; m2 = fmaxf(m2, v[i]); }
        #pragma unroll
        for (int o = 16; o > 0; o >>= 1)
            m2 = fmaxf(m2, __shfl_xor_sync(0xffffffffu, m2, o));

        float p[8], Ssum = 0.f;
        #pragma unroll
        for (int i = 0; i < 8; i++) { p[i] = expf(v[i] - m2); Ssum += p[i]; }
        #pragma unroll
        for (int o = 16; o > 0; o >>= 1)
            Ssum += __shfl_xor_sync(0xffffffffu, Ssum, o);

        float inv = 1.f / Ssum;
        #pragma unroll
        for (int i = 0; i < 8; i++) acc[i] += p[i] * inv;
    }

    float* out = g_attn + (size_t)gwarp * CHAN + lane * 8;
    *(float4*)&out[0] = make_float4(acc[0], acc[1], acc[2], acc[3]);
    *(float4*)&out[4] = make_float4(acc[4], acc[5], acc[6], acc[7]);
}

// ---------------------------------------------------------------------------
// Kernels 3/4: TN GEMM, C[m][n] = sum_k A[m][k]*B[k][n], K=256.
// 4x8 micro-tile; accumulators packed along n (n-pairs free from LDS.128 of
// the natural-layout B tile); a broadcast via MOV.
// ---------------------------------------------------------------------------
template<int NCOLS, bool FINAL>
__global__ __launch_bounds__(256, 2)
void gemm_tn(const float* __restrict__ Ab, long aStride,
             const float* __restrict__ Bb, long bStride,
             float* __restrict__ Ob,
             const float* __restrict__ bias,
             const float* __restrict__ gamma_p,
             const float* __restrict__ resid)
{
    constexpr int TM = 64, TN = 128, TK = 16, Kdim = 256, PA = 68;
    constexpr int NT = NCOLS / TN;
    __shared__ float As[TK * PA];
    __shared__ float Bs[TK * TN];

    int id = blockIdx.x;
    int nt = id % NT; id /= NT;
    int mt = id & 3;
    int b  = id >> 2;
    int mBase = mt * TM, nBase = nt * TN;

    const float* A = Ab + (size_t)b * aStride;
    const float* B = Bb + (size_t)b * bStride;
    float* O = Ob + (size_t)b * ((size_t)CHAN * NCOLS);
    const float* R = FINAL ? (resid + (size_t)b * ((size_t)CHAN * NCOLS)) : nullptr;

    int tid = threadIdx.x;
    int ty = tid >> 4, tx = tid & 15;
    int m0 = ty * 4, n0 = tx * 4;

    int mldA = tid >> 2, kcA = (tid & 3) * 4;
    int krB = tid >> 5, nvB = tid & 31;

    const float* pA  = A + (size_t)(mBase + mldA) * Kdim + kcA;
    const float* pB0 = B + (size_t)krB * NCOLS + nBase + nvB * 4;
    const float* pB1 = pB0 + (size_t)8 * NCOLS;

    float4 ra  = *(const float4*)pA;
    float4 rb0 = *(const float4*)pB0;
    float4 rb1 = *(const float4*)pB1;

    // acc2[i][np]: row i x packed col-pair np
    //   np=0: cols n0+0,1   np=1: cols n0+2,3
    //   np=2: cols 64+n0+0,1  np=3: cols 64+n0+2,3
    ull acc2[4][4];
    #pragma unroll
    for (int i = 0; i < 4; i++)
        #pragma unroll
        for (int j = 0; j < 4; j++) acc2[i][j] = 0ull;

    for (int kb = 0; kb < Kdim; kb += TK) {
        As[(kcA+0)*PA + mldA] = ra.x;
        As[(kcA+1)*PA + mldA] = ra.y;
        As[(kcA+2)*PA + mldA] = ra.z;
        As[(kcA+3)*PA + mldA] = ra.w;
        *(float4*)&Bs[krB * TN + nvB * 4]       = rb0;
        *(float4*)&Bs[(krB + 8) * TN + nvB * 4] = rb1;
        __syncthreads();

        if (kb + TK < Kdim) {
            pA += TK; pB0 += (size_t)TK * NCOLS; pB1 += (size_t)TK * NCOLS;
            ra  = *(const float4*)pA;
            rb0 = *(const float4*)pB0;
            rb1 = *(const float4*)pB1;
        }

        #pragma unroll
        for (int k = 0; k < TK; k++) {
            float4 a4 = *(const float4*)&As[k*PA + m0];
            ull aa[4] = {bcast2(a4.x), bcast2(a4.y), bcast2(a4.z), bcast2(a4.w)};
            ulonglong2 bp0 = *(const ulonglong2*)&Bs[k*TN + n0];
            ulonglong2 bp1 = *(const ulonglong2*)&Bs[k*TN + 64 + n0];
            ull bp[4] = {bp0.x, bp0.y, bp1.x, bp1.y};
            #pragma unroll
            for (int i = 0; i < 4; i++)
                #pragma unroll
                for (int j = 0; j < 4; j++)
                    fma2(acc2[i][j], aa[i], bp[j]);
        }
        __syncthreads();
    }

    float gamma = gamma_p[0];
    #pragma unroll
    for (int i = 0; i < 4; i++) {
        int row = mBase + m0 + i;
        size_t base = (size_t)row * NCOLS + nBase + n0;
        float2 c0 = unpack2(acc2[i][0]);
        float2 c1 = unpack2(acc2[i][1]);
        float2 c2 = unpack2(acc2[i][2]);
        float2 c3 = unpack2(acc2[i][3]);
        if (FINAL) {
            float gb = gamma * bias[row];
            float4 r0 = *(const float4*)&R[base];
            float4 r1 = *(const float4*)&R[base + 64];
            *(float4*)&O[base] = make_float4(
                c0.x + gb + r0.x, c0.y + gb + r0.y,
                c1.x + gb + r0.z, c1.y + gb + r0.w);
            *(float4*)&O[base + 64] = make_float4(
                c2.x + gb + r1.x, c2.y + gb + r1.y,
                c3.x + gb + r1.z, c3.y + gb + r1.w);
        } else {
            *(float4*)&O[base] = make_float4(
                gamma*c0.x, gamma*c0.y, gamma*c1.x, gamma*c1.y);
            *(float4*)&O[base + 64] = make_float4(
                gamma*c2.x, gamma*c2.y, gamma*c3.x, gamma*c3.y);
        }
    }
}

// ---------------------------------------------------------------------------
extern "C" void kernel_launch(void* const* d_in, const int* in_sizes, int n_in,
                              void* d_out, int out_size)
{
    const float* x      = (const float*)d_in[0];
    const float* y      = (const float*)d_in[1];
    const float* z      = (const float*)d_in[2];
    const float* conv_w = (const float*)d_in[3];
    const float* conv_b = (const float*)d_in[4];
    const float* gamma  = (const float*)d_in[5];
    float* out = (float*)d_out;

    float *pAttn, *pM;
    cudaGetSymbolAddress((void**)&pAttn, g_attn);
    cudaGetSymbolAddress((void**)&pM, g_M);

    // 1) three energy GEMMs: 384 CTAs
    energy_kernel<<<3 * BATCH * 8, 256>>>(x, y, z);
    // 2) softmax + sum over sources: 4096 rows, 1 warp each
    softmax_sum_kernel<<<BATCH * CHAN / 8, 256>>>();
    // 3) M_b = gamma * conv_w @ attn_b
    gemm_tn<CHAN, false><<<BATCH * 4 * 2, 256>>>(
        conv_w, 0, pAttn, (long)CHAN * CHAN, pM, nullptr, gamma, nullptr);
    // 4) out = M_b @ x_b + gamma*conv_b + x
    gemm_tn<NPIX, true><<<BATCH * 4 * 32, 256>>>(
        pM, (long)CHAN * CHAN, x, (long)CHAN * NPIX, out, conv_b, gamma, x);
}

// round 4
// speedup vs baseline: 1.6463x; 1.0009x over previous
#include <cuda_runtime.h>
#include <math.h>

#define BATCH 16
#define CHAN  256
#define NPIX  4096

typedef unsigned long long ull;

// Scratch (allocation-free: __device__ globals)
__device__ float g_energy[3u * BATCH * CHAN * CHAN];    // 12.6 MB
__device__ float g_attn[(unsigned)BATCH * CHAN * CHAN]; // 4.2 MB
__device__ float g_M[(unsigned)BATCH * CHAN * CHAN];    // 4.2 MB

// ---- packed f32x2 helpers (FFMA2: 2 IEEE fp32 FMAs per instruction) --------
__device__ __forceinline__ ull bcast2(float v) {
    ull r;
    asm("mov.b64 %0, {%1, %1};" : "=l"(r) : "f"(v));
    return r;
}
__device__ __forceinline__ void fma2(ull& d, ull a, ull b) {
    asm("fma.rn.f32x2 %0, %1, %2, %0;" : "+l"(d) : "l"(a), "l"(b));
}
__device__ __forceinline__ float2 unpack2(ull v) {
    float2 r;
    asm("mov.b64 {%0, %1}, %2;" : "=f"(r.x), "=f"(r.y) : "l"(v));
    return r;
}

// ---------------------------------------------------------------------------
// Kernel 1: energy[s][b][c][d] = sum_n x[b,c,n] * src_s[b,d,n]   (NT GEMM)
// Tile TM=128 x TN=64 x TK=16, 256 threads, 8x4 micro-tile.
// Accumulators packed along m (m-pairs come free from LDS.128); b broadcast
// packed with one MOV each (ALU pipe).
// ---------------------------------------------------------------------------
__global__ __launch_bounds__(256, 2)
void energy_kernel(const float* __restrict__ x, const float* __restrict__ y,
                   const float* __restrict__ z)
{
    constexpr int TM = 128, TN = 64, TK = 16;
    constexpr int PA = 132, PB = 68;
    __shared__ float As[TK * PA];
    __shared__ float Bs[TK * PB];

    int id = blockIdx.x;
    int t  = id & 7;
    int bs = id >> 3;
    int b  = bs & 15;
    int s  = bs >> 4;
    int cBase = (t >> 2) * TM;
    int dBase = (t & 3) * TN;

    const float* A = x + (size_t)b * (CHAN * NPIX);
    const float* S = (s == 0 ? x : (s == 1 ? y : z)) + (size_t)b * (CHAN * NPIX);

    int tid = threadIdx.x;
    int ty = tid >> 4, tx = tid & 15;
    int m0 = ty * 8, n0 = tx * 4;

    int mld = tid >> 2;
    int kc  = (tid & 3) * 4;

    const float* pA0 = A + (size_t)(cBase + mld) * NPIX + kc;
    const float* pA1 = pA0 + (size_t)64 * NPIX;
    const float* pB  = S + (size_t)(dBase + mld) * NPIX + kc;

    float4 ra0 = *(const float4*)pA0;
    float4 ra1 = *(const float4*)pA1;
    float4 rb  = *(const float4*)pB;

    // acc2[mp][j]: packed pair (rows 2mp, 2mp+1) x col j
    ull acc2[4][4];
    #pragma unroll
    for (int i = 0; i < 4; i++)
        #pragma unroll
        for (int j = 0; j < 4; j++) acc2[i][j] = 0ull;

    for (int kb = 0; kb < NPIX; kb += TK) {
        As[(kc+0)*PA + mld] = ra0.x;
        As[(kc+1)*PA + mld] = ra0.y;
        As[(kc+2)*PA + mld] = ra0.z;
        As[(kc+3)*PA + mld] = ra0.w;
        As[(kc+0)*PA + 64 + mld] = ra1.x;
        As[(kc+1)*PA + 64 + mld] = ra1.y;
        As[(kc+2)*PA + 64 + mld] = ra1.z;
        As[(kc+3)*PA + 64 + mld] = ra1.w;
        Bs[(kc+0)*PB + mld] = rb.x;
        Bs[(kc+1)*PB + mld] = rb.y;
        Bs[(kc+2)*PB + mld] = rb.z;
        Bs[(kc+3)*PB + mld] = rb.w;
        __syncthreads();

        if (kb + TK < NPIX) {
            pA0 += TK; pA1 += TK; pB += TK;
            ra0 = *(const float4*)pA0;
            ra1 = *(const float4*)pA1;
            rb  = *(const float4*)pB;
        }

        #pragma unroll
        for (int k = 0; k < TK; k++) {
            // 8 m-values as 4 packed pairs (free reinterpret of LDS.128)
            ulonglong2 am0 = *(const ulonglong2*)&As[k*PA + m0];
            ulonglong2 am1 = *(const ulonglong2*)&As[k*PA + m0 + 4];
            ull ap[4] = {am0.x, am0.y, am1.x, am1.y};
            float4 bq = *(const float4*)&Bs[k*PB + n0];
            ull bb[4] = {bcast2(bq.x), bcast2(bq.y), bcast2(bq.z), bcast2(bq.w)};
            #pragma unroll
            for (int i = 0; i < 4; i++)
                #pragma unroll
                for (int j = 0; j < 4; j++)
                    fma2(acc2[i][j], ap[i], bb[j]);
        }
        __syncthreads();
    }

    float* E = g_energy + ((size_t)s * BATCH + b) * (CHAN * CHAN);
    #pragma unroll
    for (int mp = 0; mp < 4; mp++) {
        float2 c0 = unpack2(acc2[mp][0]);
        float2 c1 = unpack2(acc2[mp][1]);
        float2 c2 = unpack2(acc2[mp][2]);
        float2 c3 = unpack2(acc2[mp][3]);
        int r0 = cBase + m0 + 2*mp;
        *(float4*)&E[(size_t)r0 * CHAN + dBase + n0] =
            make_float4(c0.x, c1.x, c2.x, c3.x);
        *(float4*)&E[(size_t)(r0+1) * CHAN + dBase + n0] =
            make_float4(c0.y, c1.y, c2.y, c3.y);
    }
}

// ---------------------------------------------------------------------------
// Kernel 2: attn[b][c][:] = sum_s softmax(rowmax(E_s[b][c]) - E_s[b][c])
// One WARP per (b,c) row; 8 elements per lane; shuffle reductions only.
// Same arithmetic path as reference (m1, then max of m1-e).
// ---------------------------------------------------------------------------
__global__ __launch_bounds__(256)
void softmax_sum_kernel()
{
    int gwarp = (blockIdx.x * blockDim.x + threadIdx.x) >> 5;  // row = b*CHAN+c
    int lane  = threadIdx.x & 31;

    float acc[8];
    #pragma unroll
    for (int i = 0; i < 8; i++) acc[i] = 0.f;

    #pragma unroll
    for (int s = 0; s < 3; s++) {
        const float* row = g_energy + ((size_t)s * BATCH * CHAN + gwarp) * CHAN;
        float4 e0 = *(const float4*)&row[lane * 8];
        float4 e1 = *(const float4*)&row[lane * 8 + 4];
        float e[8] = {e0.x, e0.y, e0.z, e0.w, e1.x, e1.y, e1.z, e1.w};

        float m1 = e[0];
        #pragma unroll
        for (int i = 1; i < 8; i++) m1 = fmaxf(m1, e[i]);
        #pragma unroll
        for (int o = 16; o > 0; o >>= 1)
            m1 = fmaxf(m1, __shfl_xor_sync(0xffffffffu, m1, o));

        float v[8], m2 = -3.402823466e38f;
        #pragma unroll
        for (int i = 0; i < 8; i++) { v[i] = m1 - e[i]; m2 = fmaxf(m2, v[i]); }
        #pragma unroll
        for (int o = 16; o > 0; o >>= 1)
            m2 = fmaxf(m2, __shfl_xor_sync(0xffffffffu, m2, o));

        float p[8], Ssum = 0.f;
        #pragma unroll
        for (int i = 0; i < 8; i++) { p[i] = expf(v[i] - m2); Ssum += p[i]; }
        #pragma unroll
        for (int o = 16; o > 0; o >>= 1)
            Ssum += __shfl_xor_sync(0xffffffffu, Ssum, o);

        float inv = 1.f / Ssum;
        #pragma unroll
        for (int i = 0; i < 8; i++) acc[i] += p[i] * inv;
    }

    float* out = g_attn + (size_t)gwarp * CHAN + lane * 8;
    *(float4*)&out[0] = make_float4(acc[0], acc[1], acc[2], acc[3]);
    *(float4*)&out[4] = make_float4(acc[4], acc[5], acc[6], acc[7]);
}

// ---------------------------------------------------------------------------
// Kernels 3/4: TN GEMM, C[m][n] = sum_k A[m][k]*B[k][n], K=256.
// 4x8 micro-tile; accumulators packed along n (n-pairs free from LDS.128 of
// the natural-layout B tile); a broadcast via MOV.
// ---------------------------------------------------------------------------
template<int NCOLS, bool FINAL>
__global__ __launch_bounds__(256, 2)
void gemm_tn(const float* __restrict__ Ab, long aStride,
             const float* __restrict__ Bb, long bStride,
             float* __restrict__ Ob,
             const float* __restrict__ bias,
             const float* __restrict__ gamma_p,
             const float* __restrict__ resid)
{
    constexpr int TM = 64, TN = 128, TK = 16, Kdim = 256, PA = 68;
    constexpr int NT = NCOLS / TN;
    __shared__ float As[TK * PA];
    __shared__ float Bs[TK * TN];

    int id = blockIdx.x;
    int nt = id % NT; id /= NT;
    int mt = id & 3;
    int b  = id >> 2;
    int mBase = mt * TM, nBase = nt * TN;

    const float* A = Ab + (size_t)b * aStride;
    const float* B = Bb + (size_t)b * bStride;
    float* O = Ob + (size_t)b * ((size_t)CHAN * NCOLS);
    const float* R = FINAL ? (resid + (size_t)b * ((size_t)CHAN * NCOLS)) : nullptr;

    int tid = threadIdx.x;
    int ty = tid >> 4, tx = tid & 15;
    int m0 = ty * 4, n0 = tx * 4;

    int mldA = tid >> 2, kcA = (tid & 3) * 4;
    int krB = tid >> 5, nvB = tid & 31;

    const float* pA  = A + (size_t)(mBase + mldA) * Kdim + kcA;
    const float* pB0 = B + (size_t)krB * NCOLS + nBase + nvB * 4;
    const float* pB1 = pB0 + (size_t)8 * NCOLS;

    float4 ra  = *(const float4*)pA;
    float4 rb0 = *(const float4*)pB0;
    float4 rb1 = *(const float4*)pB1;

    // acc2[i][np]: row i x packed col-pair np
    //   np=0: cols n0+0,1   np=1: cols n0+2,3
    //   np=2: cols 64+n0+0,1  np=3: cols 64+n0+2,3
    ull acc2[4][4];
    #pragma unroll
    for (int i = 0; i < 4; i++)
        #pragma unroll
        for (int j = 0; j < 4; j++) acc2[i][j] = 0ull;

    for (int kb = 0; kb < Kdim; kb += TK) {
        As[(kcA+0)*PA + mldA] = ra.x;
        As[(kcA+1)*PA + mldA] = ra.y;
        As[(kcA+2)*PA + mldA] = ra.z;
        As[(kcA+3)*PA + mldA] = ra.w;
        *(float4*)&Bs[krB * TN + nvB * 4]       = rb0;
        *(float4*)&Bs[(krB + 8) * TN + nvB * 4] = rb1;
        __syncthreads();

        if (kb + TK < Kdim) {
            pA += TK; pB0 += (size_t)TK * NCOLS; pB1 += (size_t)TK * NCOLS;
            ra  = *(const float4*)pA;
            rb0 = *(const float4*)pB0;
            rb1 = *(const float4*)pB1;
        }

        #pragma unroll
        for (int k = 0; k < TK; k++) {
            float4 a4 = *(const float4*)&As[k*PA + m0];
            ull aa[4] = {bcast2(a4.x), bcast2(a4.y), bcast2(a4.z), bcast2(a4.w)};
            ulonglong2 bp0 = *(const ulonglong2*)&Bs[k*TN + n0];
            ulonglong2 bp1 = *(const ulonglong2*)&Bs[k*TN + 64 + n0];
            ull bp[4] = {bp0.x, bp0.y, bp1.x, bp1.y};
            #pragma unroll
            for (int i = 0; i < 4; i++)
                #pragma unroll
                for (int j = 0; j < 4; j++)
                    fma2(acc2[i][j], aa[i], bp[j]);
        }
        __syncthreads();
    }

    float gamma = gamma_p[0];
    #pragma unroll
    for (int i = 0; i < 4; i++) {
        int row = mBase + m0 + i;
        size_t base = (size_t)row * NCOLS + nBase + n0;
        float2 c0 = unpack2(acc2[i][0]);
        float2 c1 = unpack2(acc2[i][1]);
        float2 c2 = unpack2(acc2[i][2]);
        float2 c3 = unpack2(acc2[i][3]);
        if (FINAL) {
            float gb = gamma * bias[row];
            float4 r0 = *(const float4*)&R[base];
            float4 r1 = *(const float4*)&R[base + 64];
            *(float4*)&O[base] = make_float4(
                c0.x + gb + r0.x, c0.y + gb + r0.y,
                c1.x + gb + r0.z, c1.y + gb + r0.w);
            *(float4*)&O[base + 64] = make_float4(
                c2.x + gb + r1.x, c2.y + gb + r1.y,
                c3.x + gb + r1.z, c3.y + gb + r1.w);
        } else {
            *(float4*)&O[base] = make_float4(
                gamma*c0.x, gamma*c0.y, gamma*c1.x, gamma*c1.y);
            *(float4*)&O[base + 64] = make_float4(
                gamma*c2.x, gamma*c2.y, gamma*c3.x, gamma*c3.y);
        }
    }
}

// ---------------------------------------------------------------------------
extern "C" void kernel_launch(void* const* d_in, const int* in_sizes, int n_in,
                              void* d_out, int out_size)
{
    const float* x      = (const float*)d_in[0];
    const float* y      = (const float*)d_in[1];
    const float* z      = (const float*)d_in[2];
    const float* conv_w = (const float*)d_in[3];
    const float* conv_b = (const float*)d_in[4];
    const float* gamma  = (const float*)d_in[5];
    float* out = (float*)d_out;

    float *pAttn, *pM;
    cudaGetSymbolAddress((void**)&pAttn, g_attn);
    cudaGetSymbolAddress((void**)&pM, g_M);

    // 1) three energy GEMMs: 384 CTAs
    energy_kernel<<<3 * BATCH * 8, 256>>>(x, y, z);
    // 2) softmax + sum over sources: 4096 rows, 1 warp each
    softmax_sum_kernel<<<BATCH * CHAN / 8, 256>>>();
    // 3) M_b = gamma * conv_w @ attn_b
    gemm_tn<CHAN, false><<<BATCH * 4 * 2, 256>>>(
        conv_w, 0, pAttn, (long)CHAN * CHAN, pM, nullptr, gamma, nullptr);
    // 4) out = M_b @ x_b + gamma*conv_b + x
    gemm_tn<NPIX, true><<<BATCH * 4 * 32, 256>>>(
        pM, (long)CHAN * CHAN, x, (long)CHAN * NPIX, out, conv_b, gamma, x);
}